// round 1
// baseline (speedup 1.0000x reference)
#include <cuda_runtime.h>
#include <math.h>

#define N_NODES 8192
#define IN_DIM  512
#define H_DIM   128

// Scratch (allocation-free: __device__ globals)
__device__ float g_Wh[(size_t)N_NODES * H_DIM];   // 4 MB
__device__ float g_s[N_NODES];
__device__ float g_inv[N_NODES];

// ---------------------------------------------------------------------------
// Kernel 1: Wh = h @ W^T + b     (8192x512 @ 512x128)
// BM=64, BN=128(full), BK=32, 256 threads, 4x8 per-thread tile
// ---------------------------------------------------------------------------
__global__ __launch_bounds__(256) void k_gemm_wh(const float* __restrict__ h,
                                                 const float* __restrict__ W,
                                                 const float* __restrict__ b) {
    __shared__ float hs[64][33];
    __shared__ float ws[128][33];
    const int m0 = blockIdx.x * 64;
    const int t  = threadIdx.x;
    const int tm = t >> 4;      // 0..15
    const int tn = t & 15;      // 0..15
    float acc[4][8];
#pragma unroll
    for (int v = 0; v < 4; v++)
#pragma unroll
        for (int u = 0; u < 8; u++) acc[v][u] = 0.f;

    for (int k0 = 0; k0 < IN_DIM; k0 += 32) {
#pragma unroll
        for (int p = 0; p < 8; p++) {            // 64x32 h tile
            int idx = t + p * 256;
            int r = idx >> 5, c = idx & 31;
            hs[r][c] = h[(size_t)(m0 + r) * IN_DIM + k0 + c];
        }
#pragma unroll
        for (int p = 0; p < 16; p++) {           // 128x32 W tile
            int idx = t + p * 256;
            int r = idx >> 5, c = idx & 31;
            ws[r][c] = W[(size_t)r * IN_DIM + k0 + c];
        }
        __syncthreads();
#pragma unroll
        for (int k = 0; k < 32; k++) {
            float av[4], bv[8];
#pragma unroll
            for (int v = 0; v < 4; v++) av[v] = hs[tm * 4 + v][k];
#pragma unroll
            for (int u = 0; u < 8; u++) bv[u] = ws[tn + 16 * u][k];
#pragma unroll
            for (int v = 0; v < 4; v++)
#pragma unroll
                for (int u = 0; u < 8; u++)
                    acc[v][u] += av[v] * bv[u];
        }
        __syncthreads();
    }
#pragma unroll
    for (int v = 0; v < 4; v++) {
        int i = m0 + tm * 4 + v;
#pragma unroll
        for (int u = 0; u < 8; u++) {
            int hd = tn + 16 * u;
            g_Wh[(size_t)i * H_DIM + hd] = acc[v][u] + b[hd];
        }
    }
}

// ---------------------------------------------------------------------------
// Kernel 2: s[i] = Wh[i,:] . a    (one warp per row)
// ---------------------------------------------------------------------------
__global__ __launch_bounds__(256) void k_s(const float* __restrict__ a) {
    int warp = (blockIdx.x * blockDim.x + threadIdx.x) >> 5;
    int lane = threadIdx.x & 31;
    if (warp >= N_NODES) return;
    const float4* wh4 = (const float4*)(g_Wh + (size_t)warp * H_DIM);
    const float4* a4  = (const float4*)a;
    float4 x = wh4[lane];
    float4 y = a4[lane];
    float d = x.x * y.x + x.y * y.y + x.z * y.z + x.w * y.w;
#pragma unroll
    for (int o = 16; o; o >>= 1) d += __shfl_xor_sync(0xffffffffu, d, o);
    if (lane == 0) g_s[warp] = d;
}

// ---------------------------------------------------------------------------
// Kernel 3: inv_denom[i] = 1 / sum_j mask * exp(lrelu(s_i + s_j))
// (no max subtraction needed: |s_i+s_j| << fp32 exp range)
// ---------------------------------------------------------------------------
__global__ __launch_bounds__(256) void k_denom(const float* __restrict__ adj) {
    const int i = blockIdx.x;
    const int t = threadIdx.x;
    const float si = g_s[i];
    const float* __restrict__ row = adj + (size_t)i * N_NODES;
    float d = 0.f;
#pragma unroll 4
    for (int j = t; j < N_NODES; j += 256) {
        float av = row[j];
        if (av != 0.f) {
            float x = si + g_s[j];
            float e = x > 0.f ? x : 0.2f * x;
            d += __expf(e);
        }
    }
    __shared__ float red[256];
    red[t] = d;
    __syncthreads();
#pragma unroll
    for (int o = 128; o; o >>= 1) {
        if (t < o) red[t] += red[t + o];
        __syncthreads();
    }
    if (t == 0) g_inv[i] = (red[0] > 0.f) ? 1.f / red[0] : 0.f;
}

// ---------------------------------------------------------------------------
// Kernel 4 (fused): per 64-row block, stream j in chunks of 128:
//   alpha tile = mask*exp(lrelu(s_i+s_j))*inv_i  -> gmem + smem
//   acc[i][hd] += alpha_tile @ Wh[j-chunk]       (4x8 per-thread outer product)
//   z = sigmoid(acc)
// ---------------------------------------------------------------------------
#define RT 64
#define CT 128

__global__ __launch_bounds__(256) void k_fused(const float* __restrict__ adj,
                                               float* __restrict__ z_out,
                                               float* __restrict__ alpha_out) {
    extern __shared__ float smem[];
    float* exs  = smem;                      // [RT][CT+1]  = 64*129
    float* whs  = exs + RT * (CT + 1);       // [CT][H_DIM] = 128*128
    float* sloc = whs + CT * H_DIM;          // [RT]
    float* invl = sloc + RT;                 // [RT]

    const int t  = threadIdx.x;
    const int i0 = blockIdx.x * RT;
    if (t < RT) {
        sloc[t] = g_s[i0 + t];
        invl[t] = g_inv[i0 + t];
    }
    __syncthreads();

    const int tm   = t >> 4;        // 0..15 -> rows tm*4+v
    const int tn   = t & 15;        // 0..15 -> cols tn+16u
    const int cgen = t & (CT - 1);  // constant per thread across p (256%128==0)
    const int rg0  = t >> 7;        // 0 or 1
    const int hdld = t & (H_DIM - 1);
    const int jr0  = t >> 7;

    float acc[4][8];
#pragma unroll
    for (int v = 0; v < 4; v++)
#pragma unroll
        for (int u = 0; u < 8; u++) acc[v][u] = 0.f;

    for (int j0 = 0; j0 < N_NODES; j0 += CT) {
        const float sj = g_s[j0 + cgen];

        // phase 1: alpha tile (write to gmem + smem)
#pragma unroll
        for (int p = 0; p < RT / 2; p++) {
            int r = rg0 + 2 * p;
            float av = adj[(size_t)(i0 + r) * N_NODES + j0 + cgen];
            float ex = 0.f;
            if (av != 0.f) {
                float x = sloc[r] + sj;
                float e = x > 0.f ? x : 0.2f * x;
                ex = __expf(e) * invl[r];
            }
            alpha_out[(size_t)(i0 + r) * N_NODES + j0 + cgen] = ex;
            exs[r * (CT + 1) + cgen] = ex;
        }
        // stage Wh chunk [CT][H_DIM]
#pragma unroll
        for (int p = 0; p < CT / 2; p++) {
            int jr = jr0 + 2 * p;
            whs[jr * H_DIM + hdld] = g_Wh[(size_t)(j0 + jr) * H_DIM + hdld];
        }
        __syncthreads();

        // phase 2: acc += alpha_tile @ Wh_chunk
        for (int k = 0; k < CT; k++) {
            float bv[8], av2[4];
#pragma unroll
            for (int u = 0; u < 8; u++) bv[u] = whs[k * H_DIM + tn + 16 * u];
#pragma unroll
            for (int v = 0; v < 4; v++) av2[v] = exs[(tm * 4 + v) * (CT + 1) + k];
#pragma unroll
            for (int v = 0; v < 4; v++)
#pragma unroll
                for (int u = 0; u < 8; u++)
                    acc[v][u] += av2[v] * bv[u];
        }
        __syncthreads();
    }

    // epilogue: z = sigmoid(acc)   (alpha already includes 1/denom)
#pragma unroll
    for (int v = 0; v < 4; v++) {
        int i = i0 + tm * 4 + v;
#pragma unroll
        for (int u = 0; u < 8; u++) {
            int hd = tn + 16 * u;
            float x = acc[v][u];
            z_out[(size_t)i * H_DIM + hd] = 1.f / (1.f + __expf(-x));
        }
    }
}

// ---------------------------------------------------------------------------
extern "C" void kernel_launch(void* const* d_in, const int* in_sizes, int n_in,
                              void* d_out, int out_size) {
    const float* h   = (const float*)d_in[0];  // (8192, 512)
    const float* adj = (const float*)d_in[1];  // (8192, 8192)
    const float* W   = (const float*)d_in[2];  // (128, 512)
    const float* b   = (const float*)d_in[3];  // (128,)
    const float* a   = (const float*)d_in[4];  // (1, 128)

    float* z_out     = (float*)d_out;                       // (8192,128) first
    float* alpha_out = z_out + (size_t)N_NODES * H_DIM;     // (8192,8192) second

    k_gemm_wh<<<N_NODES / 64, 256>>>(h, W, b);
    k_s<<<N_NODES / 8, 256>>>(a);
    k_denom<<<N_NODES, 256>>>(adj);

    size_t smem_bytes = (size_t)(RT * (CT + 1) + CT * H_DIM + 2 * RT) * sizeof(float);
    cudaFuncSetAttribute(k_fused, cudaFuncAttributeMaxDynamicSharedMemorySize,
                         (int)smem_bytes);
    k_fused<<<N_NODES / RT, 256, smem_bytes>>>(adj, z_out, alpha_out);
}

// round 2
// speedup vs baseline: 4.8428x; 4.8428x over previous
#include <cuda_runtime.h>
#include <cuda_bf16.h>
#include <math.h>

#define N_NODES 8192
#define IN_DIM  512
#define H_DIM   128

// Scratch (allocation-free: __device__ globals)
__device__ float        g_Wh [(size_t)N_NODES * H_DIM];  // 4 MB fp32 (for s/denom)
__device__ __nv_bfloat16 g_Whb[(size_t)N_NODES * H_DIM]; // 2 MB bf16 (MMA B operand)
__device__ float        g_s  [N_NODES];
__device__ float        g_inv[N_NODES];

// ---------------------------------------------------------------------------
// Kernel 1: Wh = h @ W^T + b     (8192x512 @ 512x128), fp32 + bf16 stores
// ---------------------------------------------------------------------------
__global__ __launch_bounds__(256) void k_gemm_wh(const float* __restrict__ h,
                                                 const float* __restrict__ W,
                                                 const float* __restrict__ b) {
    __shared__ float hs[64][33];
    __shared__ float ws[128][33];
    const int m0 = blockIdx.x * 64;
    const int t  = threadIdx.x;
    const int tm = t >> 4;
    const int tn = t & 15;
    float acc[4][8];
#pragma unroll
    for (int v = 0; v < 4; v++)
#pragma unroll
        for (int u = 0; u < 8; u++) acc[v][u] = 0.f;

    for (int k0 = 0; k0 < IN_DIM; k0 += 32) {
#pragma unroll
        for (int p = 0; p < 8; p++) {
            int idx = t + p * 256;
            int r = idx >> 5, c = idx & 31;
            hs[r][c] = h[(size_t)(m0 + r) * IN_DIM + k0 + c];
        }
#pragma unroll
        for (int p = 0; p < 16; p++) {
            int idx = t + p * 256;
            int r = idx >> 5, c = idx & 31;
            ws[r][c] = W[(size_t)r * IN_DIM + k0 + c];
        }
        __syncthreads();
#pragma unroll
        for (int k = 0; k < 32; k++) {
            float av[4], bv[8];
#pragma unroll
            for (int v = 0; v < 4; v++) av[v] = hs[tm * 4 + v][k];
#pragma unroll
            for (int u = 0; u < 8; u++) bv[u] = ws[tn + 16 * u][k];
#pragma unroll
            for (int v = 0; v < 4; v++)
#pragma unroll
                for (int u = 0; u < 8; u++)
                    acc[v][u] += av[v] * bv[u];
        }
        __syncthreads();
    }
#pragma unroll
    for (int v = 0; v < 4; v++) {
        int i = m0 + tm * 4 + v;
#pragma unroll
        for (int u = 0; u < 8; u++) {
            int hd = tn + 16 * u;
            float val = acc[v][u] + b[hd];
            g_Wh [(size_t)i * H_DIM + hd] = val;
            g_Whb[(size_t)i * H_DIM + hd] = __float2bfloat16(val);
        }
    }
}

// ---------------------------------------------------------------------------
// Kernel 2: s[i] = Wh[i,:] . a    (one warp per row)
// ---------------------------------------------------------------------------
__global__ __launch_bounds__(256) void k_s(const float* __restrict__ a) {
    int warp = (blockIdx.x * blockDim.x + threadIdx.x) >> 5;
    int lane = threadIdx.x & 31;
    if (warp >= N_NODES) return;
    const float4* wh4 = (const float4*)(g_Wh + (size_t)warp * H_DIM);
    const float4* a4  = (const float4*)a;
    float4 x = wh4[lane];
    float4 y = a4[lane];
    float d = x.x * y.x + x.y * y.y + x.z * y.z + x.w * y.w;
#pragma unroll
    for (int o = 16; o; o >>= 1) d += __shfl_xor_sync(0xffffffffu, d, o);
    if (lane == 0) g_s[warp] = d;
}

// ---------------------------------------------------------------------------
// Kernel 3: inv_denom[i] = 1 / sum_j mask * exp(lrelu(s_i + s_j))
// ---------------------------------------------------------------------------
__global__ __launch_bounds__(256) void k_denom(const float* __restrict__ adj) {
    const int i = blockIdx.x;
    const int t = threadIdx.x;
    const float si = g_s[i];
    const float4* __restrict__ row4 = (const float4*)(adj + (size_t)i * N_NODES);
    const float4* __restrict__ s4   = (const float4*)g_s;
    float d = 0.f;
#pragma unroll 4
    for (int j4 = t; j4 < N_NODES / 4; j4 += 256) {
        float4 a4 = row4[j4];
        float4 sj = s4[j4];
        float x0 = si + sj.x, x1 = si + sj.y, x2 = si + sj.z, x3 = si + sj.w;
        x0 = x0 > 0.f ? x0 : 0.2f * x0;
        x1 = x1 > 0.f ? x1 : 0.2f * x1;
        x2 = x2 > 0.f ? x2 : 0.2f * x2;
        x3 = x3 > 0.f ? x3 : 0.2f * x3;
        if (a4.x != 0.f) d += __expf(x0);
        if (a4.y != 0.f) d += __expf(x1);
        if (a4.z != 0.f) d += __expf(x2);
        if (a4.w != 0.f) d += __expf(x3);
    }
#pragma unroll
    for (int o = 16; o; o >>= 1) d += __shfl_xor_sync(0xffffffffu, d, o);
    __shared__ float red[8];
    if ((t & 31) == 0) red[t >> 5] = d;
    __syncthreads();
    if (t == 0) {
        float tot = 0.f;
#pragma unroll
        for (int w = 0; w < 8; w++) tot += red[w];
        g_inv[i] = (tot > 0.f) ? 1.f / tot : 0.f;
    }
}

// ---------------------------------------------------------------------------
// Kernel 4 (fused, tensor-core): per 32-row block, stream j in chunks of 128:
//   alpha tile (fp32) -> gmem, bf16 -> smem A
//   Wh chunk (bf16, L2-resident) -> smem B
//   acc += A @ B via mma.sync.m16n8k16 bf16
//   z = sigmoid(acc)
// ---------------------------------------------------------------------------
#define RT 32
#define CT 128
#define APAD 136   // row stride in bf16 elems (272 B): conflict-free ldmatrix

__device__ __forceinline__ void mma16816(float* c, const unsigned* a,
                                         unsigned b0, unsigned b1) {
    asm volatile(
        "mma.sync.aligned.m16n8k16.row.col.f32.bf16.bf16.f32 "
        "{%0,%1,%2,%3}, {%4,%5,%6,%7}, {%8,%9}, {%0,%1,%2,%3};"
        : "+f"(c[0]), "+f"(c[1]), "+f"(c[2]), "+f"(c[3])
        : "r"(a[0]), "r"(a[1]), "r"(a[2]), "r"(a[3]), "r"(b0), "r"(b1));
}

__global__ __launch_bounds__(256) void k_fused(const float* __restrict__ adj,
                                               float* __restrict__ z_out,
                                               float* __restrict__ alpha_out) {
    __shared__ __align__(16) __nv_bfloat16 As[RT][APAD];
    __shared__ __align__(16) __nv_bfloat16 Bs[CT][APAD];
    __shared__ float sloc[RT], invl[RT];

    const int t    = threadIdx.x;
    const int lane = t & 31;
    const int wid  = t >> 5;
    const int i0   = blockIdx.x * RT;

    if (t < RT) {
        sloc[t] = g_s[i0 + t];
        invl[t] = g_inv[i0 + t];
    }
    __syncthreads();

    const int wm = wid >> 2;   // 0..1  -> rows wm*16
    const int wn = wid & 3;    // 0..3  -> cols wn*32

    float acc[4][4];
#pragma unroll
    for (int n = 0; n < 4; n++)
#pragma unroll
        for (int c = 0; c < 4; c++) acc[n][c] = 0.f;

    const unsigned as_base = (unsigned)__cvta_generic_to_shared(&As[0][0]);
    const unsigned bs_base = (unsigned)__cvta_generic_to_shared(&Bs[0][0]);
    const int ROWB = APAD * 2;  // 272 bytes

    // ldmatrix lane addressing
    const unsigned a_addr0 = as_base + (wm * 16 + (lane & 15)) * ROWB
                                     + ((lane >> 4) * 8) * 2;
    const unsigned b_rowsel = (lane & 15);
    const unsigned b_colsel = (lane >> 4) * 8;

    for (int j0 = 0; j0 < N_NODES; j0 += CT) {
        // ---- phase 1: alpha tile ----
        const float4* s4 = (const float4*)(g_s + j0);
#pragma unroll
        for (int p = 0; p < 4; p++) {
            int idx = t + p * 256;           // 0..1023
            int r = idx >> 5, c4 = idx & 31; // row, float4-col
            float4 a4 = ((const float4*)(adj + (size_t)(i0 + r) * N_NODES + j0))[c4];
            float4 sj = s4[c4];
            float si = sloc[r], inv = invl[r];
            float4 ex;
            {
                float x = si + sj.x; x = x > 0.f ? x : 0.2f * x;
                ex.x = (a4.x != 0.f) ? __expf(x) * inv : 0.f;
            }
            {
                float x = si + sj.y; x = x > 0.f ? x : 0.2f * x;
                ex.y = (a4.y != 0.f) ? __expf(x) * inv : 0.f;
            }
            {
                float x = si + sj.z; x = x > 0.f ? x : 0.2f * x;
                ex.z = (a4.z != 0.f) ? __expf(x) * inv : 0.f;
            }
            {
                float x = si + sj.w; x = x > 0.f ? x : 0.2f * x;
                ex.w = (a4.w != 0.f) ? __expf(x) * inv : 0.f;
            }
            ((float4*)(alpha_out + (size_t)(i0 + r) * N_NODES + j0))[c4] = ex;
            __nv_bfloat162* dst = (__nv_bfloat162*)&As[r][c4 * 4];
            dst[0] = __float22bfloat162_rn(make_float2(ex.x, ex.y));
            dst[1] = __float22bfloat162_rn(make_float2(ex.z, ex.w));
        }
        // ---- stage Wh chunk (bf16, 128x128) ----
        const uint4* wb4 = (const uint4*)(g_Whb + (size_t)j0 * H_DIM);
#pragma unroll
        for (int p = 0; p < 8; p++) {
            int idx = t + p * 256;           // 0..2047
            int jr = idx >> 4, u = idx & 15; // row, uint4-col
            *(uint4*)&Bs[jr][u * 8] = wb4[idx];
        }
        __syncthreads();

        // ---- phase 2: MMA ----
#pragma unroll
        for (int kk = 0; kk < CT; kk += 16) {
            unsigned a[4];
            asm volatile(
                "ldmatrix.sync.aligned.m8n8.x4.shared.b16 {%0,%1,%2,%3}, [%4];"
                : "=r"(a[0]), "=r"(a[1]), "=r"(a[2]), "=r"(a[3])
                : "r"(a_addr0 + kk * 2));
#pragma unroll
            for (int half = 0; half < 2; half++) {
                int n0 = wn * 32 + half * 16;
                unsigned baddr = bs_base + (kk + b_rowsel) * ROWB
                                         + (n0 + b_colsel) * 2;
                unsigned b[4];
                asm volatile(
                    "ldmatrix.sync.aligned.m8n8.x4.trans.shared.b16 "
                    "{%0,%1,%2,%3}, [%4];"
                    : "=r"(b[0]), "=r"(b[1]), "=r"(b[2]), "=r"(b[3])
                    : "r"(baddr));
                mma16816(acc[half * 2 + 0], a, b[0], b[1]);
                mma16816(acc[half * 2 + 1], a, b[2], b[3]);
            }
        }
        __syncthreads();
    }

    // ---- epilogue: z = sigmoid(acc) ----
    const int g = lane >> 2, q = lane & 3;
    const size_t r0 = (size_t)(i0 + wm * 16 + g) * H_DIM;
    const size_t r1 = r0 + 8 * H_DIM;
#pragma unroll
    for (int nt = 0; nt < 4; nt++) {
        int col = wn * 32 + nt * 8 + 2 * q;
        z_out[r0 + col]     = 1.f / (1.f + __expf(-acc[nt][0]));
        z_out[r0 + col + 1] = 1.f / (1.f + __expf(-acc[nt][1]));
        z_out[r1 + col]     = 1.f / (1.f + __expf(-acc[nt][2]));
        z_out[r1 + col + 1] = 1.f / (1.f + __expf(-acc[nt][3]));
    }
}

// ---------------------------------------------------------------------------
extern "C" void kernel_launch(void* const* d_in, const int* in_sizes, int n_in,
                              void* d_out, int out_size) {
    const float* h   = (const float*)d_in[0];  // (8192, 512)
    const float* adj = (const float*)d_in[1];  // (8192, 8192)
    const float* W   = (const float*)d_in[2];  // (128, 512)
    const float* b   = (const float*)d_in[3];  // (128,)
    const float* a   = (const float*)d_in[4];  // (1, 128)

    float* z_out     = (float*)d_out;
    float* alpha_out = z_out + (size_t)N_NODES * H_DIM;

    k_gemm_wh<<<N_NODES / 64, 256>>>(h, W, b);
    k_s<<<N_NODES / 8, 256>>>(a);
    k_denom<<<N_NODES, 256>>>(adj);
    k_fused<<<N_NODES / RT, 256>>>(adj, z_out, alpha_out);
}

// round 3
// speedup vs baseline: 5.1808x; 1.0698x over previous
#include <cuda_runtime.h>
#include <cuda_bf16.h>
#include <math.h>

#define N_NODES 8192
#define IN_DIM  512
#define H_DIM   128

// Scratch (allocation-free: __device__ globals)
__device__ float         g_Wh [(size_t)N_NODES * H_DIM];  // 4 MB fp32 (for s)
__device__ __nv_bfloat16 g_Whb[(size_t)N_NODES * H_DIM];  // 2 MB bf16 (MMA B)
__device__ float         g_s  [N_NODES];

// ---------------------------------------------------------------------------
// Kernel 1: Wh = h @ W^T + b   (fp32 exact, + bf16 mirror for MMA)
// ---------------------------------------------------------------------------
__global__ __launch_bounds__(256) void k_gemm_wh(const float* __restrict__ h,
                                                 const float* __restrict__ W,
                                                 const float* __restrict__ b) {
    __shared__ float hs[64][33];
    __shared__ float ws[128][33];
    const int m0 = blockIdx.x * 64;
    const int t  = threadIdx.x;
    const int tm = t >> 4;
    const int tn = t & 15;
    float acc[4][8];
#pragma unroll
    for (int v = 0; v < 4; v++)
#pragma unroll
        for (int u = 0; u < 8; u++) acc[v][u] = 0.f;

    for (int k0 = 0; k0 < IN_DIM; k0 += 32) {
#pragma unroll
        for (int p = 0; p < 8; p++) {
            int idx = t + p * 256;
            int r = idx >> 5, c = idx & 31;
            hs[r][c] = h[(size_t)(m0 + r) * IN_DIM + k0 + c];
        }
#pragma unroll
        for (int p = 0; p < 16; p++) {
            int idx = t + p * 256;
            int r = idx >> 5, c = idx & 31;
            ws[r][c] = W[(size_t)r * IN_DIM + k0 + c];
        }
        __syncthreads();
#pragma unroll
        for (int k = 0; k < 32; k++) {
            float av[4], bv[8];
#pragma unroll
            for (int v = 0; v < 4; v++) av[v] = hs[tm * 4 + v][k];
#pragma unroll
            for (int u = 0; u < 8; u++) bv[u] = ws[tn + 16 * u][k];
#pragma unroll
            for (int v = 0; v < 4; v++)
#pragma unroll
                for (int u = 0; u < 8; u++)
                    acc[v][u] += av[v] * bv[u];
        }
        __syncthreads();
    }
#pragma unroll
    for (int v = 0; v < 4; v++) {
        int i = m0 + tm * 4 + v;
#pragma unroll
        for (int u = 0; u < 8; u++) {
            int hd = tn + 16 * u;
            float val = acc[v][u] + b[hd];
            g_Wh [(size_t)i * H_DIM + hd] = val;
            g_Whb[(size_t)i * H_DIM + hd] = __float2bfloat16(val);
        }
    }
}

// ---------------------------------------------------------------------------
// Kernel 2: s[i] = Wh[i,:] . a
// ---------------------------------------------------------------------------
__global__ __launch_bounds__(256) void k_s(const float* __restrict__ a) {
    int warp = (blockIdx.x * blockDim.x + threadIdx.x) >> 5;
    int lane = threadIdx.x & 31;
    if (warp >= N_NODES) return;
    const float4* wh4 = (const float4*)(g_Wh + (size_t)warp * H_DIM);
    const float4* a4  = (const float4*)a;
    float4 x = wh4[lane];
    float4 y = a4[lane];
    float d = x.x * y.x + x.y * y.y + x.z * y.z + x.w * y.w;
#pragma unroll
    for (int o = 16; o; o >>= 1) d += __shfl_xor_sync(0xffffffffu, d, o);
    if (lane == 0) g_s[warp] = d;
}

// ---------------------------------------------------------------------------
// Kernel 3 (fused): per-CTA denom pass over its 32 rows, then pipelined
// alpha+MMA loop: adj prefetched to registers, Wh double-buffered cp.async.
// ---------------------------------------------------------------------------
#define RT 32
#define CT 128
#define APAD 136                 // bf16 elems per row (272 B)
#define ROWB (APAD * 2)
#define AS_BYTES (RT * APAD * 2)         // 8704
#define BS_BYTES (CT * APAD * 2)         // 34816
#define SMEM_TOTAL (AS_BYTES + 2 * BS_BYTES + 3 * RT * 4)

__device__ __forceinline__ void mma16816(float* c, const unsigned* a,
                                         unsigned b0, unsigned b1) {
    asm volatile(
        "mma.sync.aligned.m16n8k16.row.col.f32.bf16.bf16.f32 "
        "{%0,%1,%2,%3}, {%4,%5,%6,%7}, {%8,%9}, {%0,%1,%2,%3};"
        : "+f"(c[0]), "+f"(c[1]), "+f"(c[2]), "+f"(c[3])
        : "r"(a[0]), "r"(a[1]), "r"(a[2]), "r"(a[3]), "r"(b0), "r"(b1));
}

__device__ __forceinline__ void cp16(unsigned dst, const void* src) {
    asm volatile("cp.async.cg.shared.global [%0], [%1], 16;\n"
                 :: "r"(dst), "l"(src));
}

__global__ __launch_bounds__(256) void k_fused(const float* __restrict__ adj,
                                               float* __restrict__ z_out,
                                               float* __restrict__ alpha_out) {
    extern __shared__ char smem[];
    __nv_bfloat16* As = (__nv_bfloat16*)smem;
    __nv_bfloat16* Bs = (__nv_bfloat16*)(smem + AS_BYTES);
    float* sloc = (float*)(smem + AS_BYTES + 2 * BS_BYTES);
    float* invl = sloc + RT;
    float* dred = invl + RT;

    const int t    = threadIdx.x;
    const int lane = t & 31;
    const int wid  = t >> 5;
    const int i0   = blockIdx.x * RT;

    if (t < RT) sloc[t] = g_s[i0 + t];

    const unsigned as_base = (unsigned)__cvta_generic_to_shared(As);
    const unsigned bs_base = (unsigned)__cvta_generic_to_shared(Bs);

    // ---- prologue: prefetch adj chunk 0 (regs) + Wh chunk 0 (cp.async) ----
    float4 pfa[4];
#pragma unroll
    for (int p = 0; p < 4; p++) {
        int idx = t + p * 256;
        int r = idx >> 5, c4 = idx & 31;
        pfa[p] = __ldcg((const float4*)(adj + (size_t)(i0 + r) * N_NODES) + c4);
    }
#pragma unroll
    for (int p = 0; p < 8; p++) {
        int idx = t + p * 256;          // 0..2047
        int jr = idx >> 4, u = idx & 15;
        cp16(bs_base + jr * ROWB + u * 16, (const char*)g_Whb + idx * 16);
    }
    asm volatile("cp.async.commit_group;");

    // ---- denom pass: rows i0..i0+31, 8 threads per row ----
    {
        const int dr = t >> 3, dcg = t & 7;
        const float dsi = __ldg(&g_s[i0 + dr]);
        const float4* drow = (const float4*)(adj + (size_t)(i0 + dr) * N_NODES);
        const float4* s4g  = (const float4*)g_s;
        float dsum = 0.f;
#pragma unroll 4
        for (int c4 = dcg; c4 < N_NODES / 4; c4 += 8) {
            float4 a4 = __ldcg(&drow[c4]);
            float4 sj = __ldg(&s4g[c4]);
            float x0 = dsi + sj.x, x1 = dsi + sj.y;
            float x2 = dsi + sj.z, x3 = dsi + sj.w;
            x0 = x0 > 0.f ? x0 : 0.2f * x0;
            x1 = x1 > 0.f ? x1 : 0.2f * x1;
            x2 = x2 > 0.f ? x2 : 0.2f * x2;
            x3 = x3 > 0.f ? x3 : 0.2f * x3;
            if (a4.x != 0.f) dsum += __expf(x0);
            if (a4.y != 0.f) dsum += __expf(x1);
            if (a4.z != 0.f) dsum += __expf(x2);
            if (a4.w != 0.f) dsum += __expf(x3);
        }
#pragma unroll
        for (int o = 4; o; o >>= 1)
            dsum += __shfl_down_sync(0xffffffffu, dsum, o, 8);
        if (dcg == 0) dred[dr] = dsum;
    }
    __syncthreads();
    if (t < RT) invl[t] = (dred[t] > 0.f) ? 1.f / dred[t] : 0.f;
    __syncthreads();

    // ---- main pipelined loop ----
    const int wm = wid >> 2;   // 0..1
    const int wn = wid & 3;    // 0..3
    float acc[4][4];
#pragma unroll
    for (int n = 0; n < 4; n++)
#pragma unroll
        for (int c = 0; c < 4; c++) acc[n][c] = 0.f;

    const unsigned a_addr0 = as_base + (wm * 16 + (lane & 15)) * ROWB
                                     + ((lane >> 4) * 8) * 2;
    const unsigned b_rowsel = (lane & 15);
    const unsigned b_colsel = (lane >> 4) * 8;
    const float4* s4g = (const float4*)g_s;

    for (int c = 0; c < N_NODES / CT; c++) {
        const int j0  = c * CT;
        const int buf = c & 1;

        // phase 1: consume prefetched adj -> alpha (gmem) + As (smem bf16)
#pragma unroll
        for (int p = 0; p < 4; p++) {
            int idx = t + p * 256;
            int r = idx >> 5, c4 = idx & 31;
            float4 a4 = pfa[p];
            float4 sj = __ldg(&s4g[j0 / 4 + c4]);
            float si = sloc[r], inv = invl[r];
            float4 ex;
            {
                float x = si + sj.x; x = x > 0.f ? x : 0.2f * x;
                ex.x = (a4.x != 0.f) ? __expf(x) * inv : 0.f;
            }
            {
                float x = si + sj.y; x = x > 0.f ? x : 0.2f * x;
                ex.y = (a4.y != 0.f) ? __expf(x) * inv : 0.f;
            }
            {
                float x = si + sj.z; x = x > 0.f ? x : 0.2f * x;
                ex.z = (a4.z != 0.f) ? __expf(x) * inv : 0.f;
            }
            {
                float x = si + sj.w; x = x > 0.f ? x : 0.2f * x;
                ex.w = (a4.w != 0.f) ? __expf(x) * inv : 0.f;
            }
            __stcs((float4*)(alpha_out + (size_t)(i0 + r) * N_NODES + j0) + c4, ex);
            __nv_bfloat162* dst = (__nv_bfloat162*)&As[r * APAD + c4 * 4];
            dst[0] = __float22bfloat162_rn(make_float2(ex.x, ex.y));
            dst[1] = __float22bfloat162_rn(make_float2(ex.z, ex.w));
        }

        // prefetch next chunk (adj -> regs, Wh -> other smem buffer)
        if (c + 1 < N_NODES / CT) {
            const int jn = (c + 1) * CT;
#pragma unroll
            for (int p = 0; p < 4; p++) {
                int idx = t + p * 256;
                int r = idx >> 5, c4 = idx & 31;
                pfa[p] = __ldcg((const float4*)(adj + (size_t)(i0 + r) * N_NODES + jn) + c4);
            }
            const char* src = (const char*)(g_Whb + (size_t)jn * H_DIM);
            const unsigned bdst = bs_base + (buf ^ 1) * BS_BYTES;
#pragma unroll
            for (int p = 0; p < 8; p++) {
                int idx = t + p * 256;
                int jr = idx >> 4, u = idx & 15;
                cp16(bdst + jr * ROWB + u * 16, src + idx * 16);
            }
            asm volatile("cp.async.commit_group;");
            asm volatile("cp.async.wait_group 1;");
        } else {
            asm volatile("cp.async.wait_group 0;");
        }
        __syncthreads();

        // phase 2: MMA on As x Bs[buf]
        const unsigned bbuf = bs_base + buf * BS_BYTES;
#pragma unroll
        for (int kk = 0; kk < CT; kk += 16) {
            unsigned a[4];
            asm volatile(
                "ldmatrix.sync.aligned.m8n8.x4.shared.b16 {%0,%1,%2,%3}, [%4];"
                : "=r"(a[0]), "=r"(a[1]), "=r"(a[2]), "=r"(a[3])
                : "r"(a_addr0 + kk * 2));
#pragma unroll
            for (int half = 0; half < 2; half++) {
                int n0 = wn * 32 + half * 16;
                unsigned baddr = bbuf + (kk + b_rowsel) * ROWB
                                      + (n0 + b_colsel) * 2;
                unsigned b[4];
                asm volatile(
                    "ldmatrix.sync.aligned.m8n8.x4.trans.shared.b16 "
                    "{%0,%1,%2,%3}, [%4];"
                    : "=r"(b[0]), "=r"(b[1]), "=r"(b[2]), "=r"(b[3])
                    : "r"(baddr));
                mma16816(acc[half * 2 + 0], a, b[0], b[1]);
                mma16816(acc[half * 2 + 1], a, b[2], b[3]);
            }
        }
        __syncthreads();
    }

    // ---- epilogue: z = sigmoid(acc) ----
    const int g = lane >> 2, q = lane & 3;
    const size_t r0 = (size_t)(i0 + wm * 16 + g) * H_DIM;
    const size_t r1 = r0 + 8 * H_DIM;
#pragma unroll
    for (int nt = 0; nt < 4; nt++) {
        int col = wn * 32 + nt * 8 + 2 * q;
        z_out[r0 + col]     = 1.f / (1.f + __expf(-acc[nt][0]));
        z_out[r0 + col + 1] = 1.f / (1.f + __expf(-acc[nt][1]));
        z_out[r1 + col]     = 1.f / (1.f + __expf(-acc[nt][2]));
        z_out[r1 + col + 1] = 1.f / (1.f + __expf(-acc[nt][3]));
    }
}

// ---------------------------------------------------------------------------
extern "C" void kernel_launch(void* const* d_in, const int* in_sizes, int n_in,
                              void* d_out, int out_size) {
    const float* h   = (const float*)d_in[0];  // (8192, 512)
    const float* adj = (const float*)d_in[1];  // (8192, 8192)
    const float* W   = (const float*)d_in[2];  // (128, 512)
    const float* b   = (const float*)d_in[3];  // (128,)
    const float* a   = (const float*)d_in[4];  // (1, 128)

    float* z_out     = (float*)d_out;
    float* alpha_out = z_out + (size_t)N_NODES * H_DIM;

    k_gemm_wh<<<N_NODES / 64, 256>>>(h, W, b);
    k_s<<<N_NODES / 8, 256>>>(a);

    cudaFuncSetAttribute(k_fused, cudaFuncAttributeMaxDynamicSharedMemorySize,
                         SMEM_TOTAL);
    k_fused<<<N_NODES / RT, 256, SMEM_TOTAL>>>(adj, z_out, alpha_out);
}